// round 13
// baseline (speedup 1.0000x reference)
#include <cuda_runtime.h>
#include <cstdint>

// TNorm: out[b, ((i0*8+i1)*8+i2)*8+i3] = g0[i0]*g1[i1]*g2[i2]*g3[i3], g=x[b].
// x: (16384,32) fp32 -> out: (16384,4096) fp32. 256 MiB pure write stream.
//
// Plateau model: 512MB LTS transit @ ~11.8TB/s cap -> ~43.5us floor. Dual
// STG+TMA consistently beats pure TMA by ~0.5-1us (partially separate fill
// queues ahead of LTS). R13: sweep the split fraction 0.25 -> 0.375
// (3 chunks register-direct __stcs, 5 chunks smem+TMA). LSU rate needed
// ~2.15 TB/s, just under the 2.3 TB/s LSU ceiling measured in R1.

#define BATCH       16384
#define ROW_FLOATS  4096
#define TMA_CHUNKS  5
#define TMA_FLOATS  (TMA_CHUNKS * 512)         /* 2560 */
#define TMA_BYTES   (TMA_FLOATS * 4)           /* 10KB */
#define NT          128
#define NBUF        3
#define GRID_CTAS   (148 * 5)
#define SMEM_BYTES  (NBUF * TMA_BYTES + 2 * 32 * 4)

__global__ __launch_bounds__(NT)
void tnorm_dual38_kernel(const float* __restrict__ x, float* __restrict__ out) {
    extern __shared__ float smem[];
    float* buf = smem;                        // NBUF x 2560 floats
    float* g   = smem + NBUF * TMA_FLOATS;    // 2 x 32 floats

    const int t = threadIdx.x;
    const int i1  = t >> 4;
    const int i2  = (t >> 1) & 7;
    const int i3b = (t & 1) * 4;

    uint64_t pol;
    asm volatile("createpolicy.fractional.L2::evict_first.b64 %0, 1.0;" : "=l"(pol));

    const int row0 = blockIdx.x;
    if (t < 8 && row0 < BATCH)
        reinterpret_cast<float4*>(g)[t] =
            reinterpret_cast<const float4*>(x + (size_t)row0 * 32)[t];
    __syncthreads();

    int it = 0;
    for (int row = row0; row < BATCH; row += gridDim.x, ++it) {
        float* b = buf + (it % NBUF) * TMA_FLOATS;
        const float* gc = g + (it & 1) * 32;

        if (t == 0)
            asm volatile("cp.async.bulk.wait_group.read 2;" ::: "memory");

        const int nrow = row + gridDim.x;
        if (t < 8 && nrow < BATCH)
            reinterpret_cast<float4*>(g + ((it + 1) & 1) * 32)[t] =
                reinterpret_cast<const float4*>(x + (size_t)nrow * 32)[t];

        __syncthreads();

        const float p12 = gc[8 + i1] * gc[16 + i2];
        const float4 a3 = *reinterpret_cast<const float4*>(&gc[24 + i3b]);
        float* orow = out + (size_t)row * ROW_FLOATS;

        // STG slice: chunks 5,6,7 (6KB) register-direct streaming stores.
        #pragma unroll
        for (int k = TMA_CHUNKS; k < 8; k++) {
            const float s = gc[k] * p12;
            float4 v = make_float4(s * a3.x, s * a3.y, s * a3.z, s * a3.w);
            __stcs(reinterpret_cast<float4*>(orow + k * 512 + t * 4), v);
        }

        // TMA slice: chunks 0..4 into smem, one 10KB bulk store.
        #pragma unroll
        for (int k = 0; k < TMA_CHUNKS; k++) {
            const float s = gc[k] * p12;
            float4 v = make_float4(s * a3.x, s * a3.y, s * a3.z, s * a3.w);
            *reinterpret_cast<float4*>(b + k * 512 + t * 4) = v;
        }
        __syncthreads();

        if (t == 0) {
            asm volatile("fence.proxy.async.shared::cta;" ::: "memory");
            const uint32_t saddr = (uint32_t)__cvta_generic_to_shared(b);
            asm volatile(
                "cp.async.bulk.global.shared::cta.bulk_group.L2::cache_hint "
                "[%0], [%1], %2, %3;"
                :: "l"(orow), "r"(saddr), "n"(TMA_BYTES), "l"(pol) : "memory");
            asm volatile("cp.async.bulk.commit_group;" ::: "memory");
        }
    }

    if (t == 0)
        asm volatile("cp.async.bulk.wait_group.read 0;" ::: "memory");
    __syncthreads();
}

extern "C" void kernel_launch(void* const* d_in, const int* in_sizes, int n_in,
                              void* d_out, int out_size) {
    const float* x = (const float*)d_in[0];
    float* out = (float*)d_out;
    static bool attr_set = false;
    if (!attr_set) {
        cudaFuncSetAttribute(tnorm_dual38_kernel,
                             cudaFuncAttributeMaxDynamicSharedMemorySize,
                             SMEM_BYTES);
        attr_set = true;
    }
    tnorm_dual38_kernel<<<GRID_CTAS, NT, SMEM_BYTES>>>(x, out);
}

// round 14
// speedup vs baseline: 1.0035x; 1.0035x over previous
#include <cuda_runtime.h>
#include <cstdint>

// TNorm: out[b, ((i0*8+i1)*8+i2)*8+i3] = g0[i0]*g1[i1]*g2[i2]*g3[i3], g=x[b].
// x: (16384,32) fp32 -> out: (16384,4096) fp32. 256 MiB pure write stream.
//
// FINAL (converged, 12 variants). Wall: every output byte transits LTS twice
// (SM->L2 fill + dirty drain) = 512MB/replay at the ~11.8TB/s LTS cap ->
// ~43.5us floor. Closed axes: L2 bypass (no_allocate: no compile; .wt:
// demoted -2us), cross-replay retention (neutral), issue shaping / warp
// decoupling / tile size (neutral), STG:TMA split fraction (f=0 45.3-45.7,
// f=0.25 44.7 OPTIMAL, f=0.375 45.7 = LSU cap). This kernel: dual-path
// f=0.25 — 12KB/row via smem + TMA bulk store (evict_first), 4KB/row
// register-direct __stcs; triple-buffered, persistent, x-row prefetch.

#define BATCH       16384
#define ROW_FLOATS  4096
#define TMA_CHUNKS  6
#define TMA_FLOATS  (TMA_CHUNKS * 512)         /* 3072 */
#define TMA_BYTES   (TMA_FLOATS * 4)           /* 12KB */
#define NT          128
#define NBUF        3
#define GRID_CTAS   (148 * 5)
#define SMEM_BYTES  (NBUF * TMA_BYTES + 2 * 32 * 4)

__global__ __launch_bounds__(NT)
void tnorm_dual_kernel(const float* __restrict__ x, float* __restrict__ out) {
    extern __shared__ float smem[];
    float* buf = smem;                        // NBUF x 3072 floats
    float* g   = smem + NBUF * TMA_FLOATS;    // 2 x 32 floats

    const int t = threadIdx.x;
    const int i1  = t >> 4;
    const int i2  = (t >> 1) & 7;
    const int i3b = (t & 1) * 4;

    uint64_t pol;
    asm volatile("createpolicy.fractional.L2::evict_first.b64 %0, 1.0;" : "=l"(pol));

    const int row0 = blockIdx.x;
    if (t < 8 && row0 < BATCH)
        reinterpret_cast<float4*>(g)[t] =
            reinterpret_cast<const float4*>(x + (size_t)row0 * 32)[t];
    __syncthreads();

    int it = 0;
    for (int row = row0; row < BATCH; row += gridDim.x, ++it) {
        float* b = buf + (it % NBUF) * TMA_FLOATS;
        const float* gc = g + (it & 1) * 32;

        // Buffer reuse guard: group issued NBUF iters ago must be smem-read done.
        if (t == 0)
            asm volatile("cp.async.bulk.wait_group.read 2;" ::: "memory");

        // Prefetch next row's 32 inputs (hidden behind this iteration).
        const int nrow = row + gridDim.x;
        if (t < 8 && nrow < BATCH)
            reinterpret_cast<float4*>(g + ((it + 1) & 1) * 32)[t] =
                reinterpret_cast<const float4*>(x + (size_t)nrow * 32)[t];

        __syncthreads();

        const float p12 = gc[8 + i1] * gc[16 + i2];
        const float4 a3 = *reinterpret_cast<const float4*>(&gc[24 + i3b]);
        float* orow = out + (size_t)row * ROW_FLOATS;

        // STG slice (f=0.25): chunks 6,7 register-direct streaming stores.
        #pragma unroll
        for (int k = TMA_CHUNKS; k < 8; k++) {
            const float s = gc[k] * p12;
            float4 v = make_float4(s * a3.x, s * a3.y, s * a3.z, s * a3.w);
            __stcs(reinterpret_cast<float4*>(orow + k * 512 + t * 4), v);
        }

        // TMA slice: chunks 0..5 into smem (conflict-free), one 12KB bulk store.
        #pragma unroll
        for (int k = 0; k < TMA_CHUNKS; k++) {
            const float s = gc[k] * p12;
            float4 v = make_float4(s * a3.x, s * a3.y, s * a3.z, s * a3.w);
            *reinterpret_cast<float4*>(b + k * 512 + t * 4) = v;
        }
        __syncthreads();

        if (t == 0) {
            asm volatile("fence.proxy.async.shared::cta;" ::: "memory");
            const uint32_t saddr = (uint32_t)__cvta_generic_to_shared(b);
            asm volatile(
                "cp.async.bulk.global.shared::cta.bulk_group.L2::cache_hint "
                "[%0], [%1], %2, %3;"
                :: "l"(orow), "r"(saddr), "n"(TMA_BYTES), "l"(pol) : "memory");
            asm volatile("cp.async.bulk.commit_group;" ::: "memory");
        }
    }

    // Drain all pending bulk reads before CTA exit deallocates smem.
    if (t == 0)
        asm volatile("cp.async.bulk.wait_group.read 0;" ::: "memory");
    __syncthreads();
}

extern "C" void kernel_launch(void* const* d_in, const int* in_sizes, int n_in,
                              void* d_out, int out_size) {
    const float* x = (const float*)d_in[0];
    float* out = (float*)d_out;
    static bool attr_set = false;
    if (!attr_set) {
        cudaFuncSetAttribute(tnorm_dual_kernel,
                             cudaFuncAttributeMaxDynamicSharedMemorySize,
                             SMEM_BYTES);
        attr_set = true;
    }
    tnorm_dual_kernel<<<GRID_CTAS, NT, SMEM_BYTES>>>(x, out);
}